// round 9
// baseline (speedup 1.0000x reference)
#include <cuda_runtime.h>

typedef unsigned long long u64;
typedef unsigned int u32;

#define NB        8
#define NCLS      80
#define NCLASSES  (NB * NCLS)      // 640
#define KCAND     256
#define MAXPC     8
#define CSTRIDE32 1280             // u32 slots per class (= 640 u64 for fallback view)
#define CAPSC     128              // trusted capture bound (E=64, sigma=8)
#define KRC       4                // keys/lane, common path (u32)
#define KRF       20               // keys/lane, fallback path (u64)
#define LOCCAP    8
#define CHUNK     256
#define THR       0.9968f          // E[captures/class] = 64
#define SBASE     0x3F7F0000u      // float bits base for 16-bit score packing
#define WPB       5                // warps per NMS CTA -> grid 128
#define NBUCKETS  1024
#define BATCH     16
#define FULLM     0xFFFFFFFFu

static __device__ u32    g_cand[NCLASSES * CSTRIDE32];  // 3.3 MB scratch
static __device__ int    g_cnt[NCLASSES];               // reset by finisher each launch
static __device__ u64    g_keys[NCLASSES * MAXPC];      // (score<<32)|((0x7FFF-flat)<<16)|pos
static __device__ float4 g_boxes[NCLASSES * MAXPC];
static __device__ u32    g_done;

__device__ __forceinline__ float clamp01(float x) { return fminf(fmaxf(x, 0.0f), 1.0f); }

// ---- key adapters: u32 packed (common) / u64 (fallback) -------------------
__device__ __forceinline__ u32 warpmaxk(u32 v) { return __reduce_max_sync(FULLM, v); }
__device__ __forceinline__ u64 warpmaxk(u64 v)
{
    u32 hi = (u32)(v >> 32);
    u32 hmax = __reduce_max_sync(FULLM, hi);
    u32 lo = (hi == hmax) ? (u32)v : 0u;
    u32 lmax = __reduce_max_sync(FULLM, lo);
    return ((u64)hmax << 32) | lmax;
}
__device__ __forceinline__ u32 key_scorebits(u32 k) { return (k >> 15) + SBASE; }
__device__ __forceinline__ u32 key_scorebits(u64 k) { return (u32)(k >> 32); }
__device__ __forceinline__ u32 key_box(u32 k) { return 0x7FFFu - (k & 0x7FFFu); }
__device__ __forceinline__ u32 key_box(u64 k) { return 0xFFFFFFFFu - (u32)k; }
__device__ __forceinline__ bool key_stop(u32 k) { return k == 0u; }
__device__ __forceinline__ bool key_stop(u64 k) { return (u32)(k >> 32) <= 0x3F000000u; }

// ---------------------------------------------------------------------------
// Warp-synchronous greedy NMS over a candidate list (exact rank order).
// ---------------------------------------------------------------------------
template<typename K, int KRN>
__device__ int run_nms(const float4* __restrict__ boxes4, int nbox, int b, int c,
                       const K* __restrict__ cand, int cnt, bool* ranout)
{
    const int lane = threadIdx.x & 31;

    K kr[KRN];
    #pragma unroll
    for (int r = 0; r < KRN; ++r) {
        int slot = r * 32 + lane;
        kr[r] = (slot < cnt) ? cand[slot] : (K)0;
    }
    K mymax = kr[0];
    #pragma unroll
    for (int r = 1; r < KRN; ++r) if (kr[r] > mymax) mymax = kr[r];

    float4 mykept = make_float4(0.f, 0.f, 0.f, 0.f);
    float  myka   = 0.f;
    int kc = 0, totpops = 0;
    bool more = true, exhausted = false;

    while (more && kc < MAXPC && totpops < KCAND) {
        // ---- phase 1: pop up to BATCH keys (no memory on critical path) ----
        const int lim = min(BATCH, KCAND - totpops);
        K okey = (K)0;
        int n = 0;
        for (int r = 0; r < lim; ++r) {
            K best = warpmaxk(mymax);                        // uniform
            if (key_stop(best)) { exhausted = true; break; } // uniform
            if (lane == r) okey = best;
            if (mymax == best) {   // unique owner refills its lane max
                mymax = (K)0;
                #pragma unroll
                for (int q = 0; q < KRN; ++q) {
                    if (kr[q] == best) kr[q] = (K)0;
                    if (kr[q] > mymax) mymax = kr[q];
                }
            }
            ++n;
        }
        more = (n == lim) && (lim == BATCH);

        // ---- phase 2: one parallel box gather (MLP = n) ----
        float4 obox = make_float4(0.f, 0.f, 0.f, 0.f);
        if (lane < n)
            obox = boxes4[(size_t)b * nbox + key_box(okey)];

        // ---- phase 3: shuffle-resident greedy NMS over ordered batch ----
        for (int r = 0; r < n; ++r) {
            float4 bx;
            bx.x = __shfl_sync(FULLM, obox.x, r);
            bx.y = __shfl_sync(FULLM, obox.y, r);
            bx.z = __shfl_sync(FULLM, obox.z, r);
            bx.w = __shfl_sync(FULLM, obox.w, r);
            K key = __shfl_sync(FULLM, okey, r);
            float area = fmaxf(bx.z - bx.x, 0.f) * fmaxf(bx.w - bx.y, 0.f);

            bool supme = false;
            if (lane < kc) {
                float iy1 = fmaxf(bx.x, mykept.x), ix1 = fmaxf(bx.y, mykept.y);
                float iy2 = fminf(bx.z, mykept.z), ix2 = fminf(bx.w, mykept.w);
                float inter = fmaxf(iy2 - iy1, 0.f) * fmaxf(ix2 - ix1, 0.f);
                float uni = area + myka - inter;
                float iou = (uni > 0.f) ? inter / uni : 0.f;
                supme = iou > 0.5f;
            }
            bool keep = (__ballot_sync(FULLM, supme) == 0u);   // uniform

            if (keep) {
                if (lane == kc) {
                    mykept = bx;
                    myka = area;
                    int flat = c * KCAND + totpops + r;
                    int pos  = c * MAXPC + kc;
                    g_keys[b * NCLS * MAXPC + pos] =
                        ((u64)key_scorebits(key) << 32) |
                        ((u64)(u32)(0x7FFF - flat) << 16) | (u32)pos;
                    g_boxes[b * NCLS * MAXPC + pos] = bx;
                }
                ++kc;
                if (kc >= MAXPC) return kc;    // uniform exit
            }
        }
        totpops += n;
        if (exhausted) break;
    }
    *ranout = exhausted && (kc < MAXPC) && (totpops < KCAND);
    return kc;
}

// ---------------------------------------------------------------------------
// Kernel A: coalesced MLP-4 scan; capture s >= THR as packed u32 keys.
// ---------------------------------------------------------------------------
__global__ __launch_bounds__(256) void scan_kernel(
    const float* __restrict__ scores, int nbox, int nchunks)
{
    const int tid  = threadIdx.x;
    const int b    = blockIdx.x / nchunks;
    const int ch   = blockIdx.x % nchunks;
    const int box0 = ch * CHUNK;
    const int boxN = min(CHUNK, nbox - box0);

    __shared__ u32 loc[NCLS * LOCCAP];   // 2.5 KB
    __shared__ int lcnt[NCLS];

    for (int i = tid; i < NCLS; i += 256) lcnt[i] = 0;
    __syncthreads();

    if (boxN > 0) {
        const float4* sp = reinterpret_cast<const float4*>(scores) +
                           (size_t)(b * nbox + box0) * (NCLS / 4);
        const int nf4 = boxN * (NCLS / 4);
        for (int t0 = tid; t0 < nf4; t0 += 1024) {
            float4 v[4];
            #pragma unroll
            for (int u = 0; u < 4; ++u) {
                int t = t0 + u * 256;
                v[u] = (t < nf4) ? sp[t] : make_float4(0.f, 0.f, 0.f, 0.f);
            }
            #pragma unroll
            for (int u = 0; u < 4; ++u) {
                int t = t0 + u * 256;
                if (t >= nf4) break;
                int box = box0 + t / (NCLS / 4);
                int g   = t % (NCLS / 4);
                float sv[4] = {v[u].x, v[u].y, v[u].z, v[u].w};
                #pragma unroll
                for (int k = 0; k < 4; ++k) {
                    if (sv[k] >= THR) {
                        int c = g * 4 + k;
                        u32 key = ((__float_as_uint(sv[k]) - SBASE) << 15) |
                                  (u32)(0x7FFF - box);
                        int p = atomicAdd(&lcnt[c], 1);
                        if (p < LOCCAP) {
                            loc[c * LOCCAP + p] = key;
                        } else {  // rare spill to global (set stays complete)
                            int q = atomicAdd(&g_cnt[b * NCLS + c], 1);
                            if (q < CAPSC)
                                g_cand[(size_t)(b * NCLS + c) * CSTRIDE32 + q] = key;
                        }
                    }
                }
            }
        }
    }
    __syncthreads();

    for (int c = tid; c < NCLS; c += 256) {
        int n = min(lcnt[c], LOCCAP);
        if (n > 0) {
            int base = atomicAdd(&g_cnt[b * NCLS + c], n);
            for (int j = 0; j < n; ++j) {
                int q = base + j;
                if (q < CAPSC)
                    g_cand[(size_t)(b * NCLS + c) * CSTRIDE32 + q] = loc[c * LOCCAP + j];
            }
        }
    }
}

// ---------------------------------------------------------------------------
// Kernel B: one warp per (batch,class); u32-key NMS + fused finisher.
// ---------------------------------------------------------------------------
__global__ __launch_bounds__(32 * WPB) void nms_kernel(
    const float4* __restrict__ boxes4,
    const float*  __restrict__ scores,
    float* __restrict__ out,
    int nbox, int force_fb)
{
    const int tid  = threadIdx.x;
    const int lane = tid & 31;
    const int wid  = tid >> 5;
    const int cls  = blockIdx.x * WPB + wid;
    const int b    = cls / NCLS;
    const int c    = cls % NCLS;

    __shared__ u32 sh_hist[WPB][NBUCKETS];   // fallback only, 20 KB
    __shared__ int sh_fc[WPB];
    __shared__ int sh_last;

    const u32* cand32 = g_cand + (size_t)cls * CSTRIDE32;
    int cnt = g_cnt[cls];
    int kc = 0;
    bool needfb = force_fb || (cnt > CAPSC) || (cnt <= 0);

    if (!needfb) {
        bool ranout = false;
        kc = run_nms<u32, KRC>(boxes4, nbox, b, c, cand32, cnt, &ranout);
        needfb = ranout;   // exhausted capture window before 8 keeps / 256 pops
    }

    if (needfb) {
        // ---- exact fallback: histogram top-256 window rescan (never expected) ----
        u64* cand64 = (u64*)cand32;   // 640 u64 slots per class
        u32* hist = sh_hist[wid];
        for (int i = lane; i < NBUCKETS; i += 32) hist[i] = 0;
        __syncwarp();
        for (int i = lane; i < nbox; i += 32) {
            float s = scores[((size_t)b * nbox + i) * NCLS + c];
            atomicAdd(&hist[min((int)(s * (float)NBUCKETS), NBUCKETS - 1)], 1u);
        }
        __syncwarp();
        const int base = lane * 32;
        u32 part = 0;
        #pragma unroll
        for (int j = 0; j < 32; ++j) part += hist[base + j];
        u32 suf = part;
        #pragma unroll
        for (int off = 16; off; off >>= 1) {
            u32 v = __shfl_down_sync(FULLM, suf, off);
            if (lane + off < 32) suf += v;
        }
        u32 above = __shfl_down_sync(FULLM, suf, 1);
        if (lane == 31) above = 0;
        int T = -1;
        u32 prev = above;
        for (int bkt = base + 31; bkt >= base; --bkt) {
            u32 cur = prev + hist[bkt];
            if (cur >= KCAND && prev < KCAND) T = bkt;
            prev = cur;
        }
        #pragma unroll
        for (int off = 16; off; off >>= 1)
            T = max(T, __shfl_xor_sync(FULLM, T, off));
        T = max(T, 0);
        if (lane == 0) sh_fc[wid] = 0;
        __syncwarp();
        for (int i = lane; i < nbox; i += 32) {
            float s = scores[((size_t)b * nbox + i) * NCLS + c];
            int bk = min((int)(s * (float)NBUCKETS), NBUCKETS - 1);
            if (bk >= T) {
                int q = atomicAdd(&sh_fc[wid], 1);
                if (q < KRF * 32)
                    cand64[q] = ((u64)__float_as_uint(s) << 32) |
                                (u32)(0xFFFFFFFFu - (u32)i);
            }
        }
        __threadfence();
        __syncwarp();
        int fcnt = min(sh_fc[wid], KRF * 32);
        bool dummy = false;
        kc = run_nms<u64, KRF>(boxes4, nbox, b, c, cand64, fcnt, &dummy);
    }

    if (lane >= kc && lane < MAXPC)
        g_keys[(size_t)cls * MAXPC + lane] = 0ull;

    // ---- fused finisher: last CTA does per-batch top-8 + counter reset ----
    __syncthreads();
    if (tid == 0) {
        __threadfence();
        sh_last = (atomicAdd(&g_done, 1u) == (u32)(gridDim.x - 1));
    }
    __syncthreads();
    if (!sh_last) return;
    if (tid == 0) g_done = 0u;
    for (int i = tid; i < NCLASSES; i += 32 * WPB) g_cnt[i] = 0;
    __threadfence();

    for (int bb = wid; bb < NB; bb += WPB) {
        // per-lane top-8 of 20 keys with fast-reject, then 8 redux merges
        u64 t[8] = {0, 0, 0, 0, 0, 0, 0, 0};
        #pragma unroll
        for (int j = 0; j < 20; ++j) {
            u64 k = g_keys[(size_t)bb * (NCLS * MAXPC) + j * 32 + lane];
            if (k > t[7]) {                       // most keys are 0: 1 compare
                #pragma unroll
                for (int p = 0; p < 8; ++p)
                    if (k > t[p]) { u64 tmp = t[p]; t[p] = k; k = tmp; }
            }
        }

        u64 mykey = 0ull;
        #pragma unroll
        for (int r = 0; r < 8; ++r) {
            u64 best = warpmaxk(t[0]);
            if (lane == r) mykey = best;
            if (t[0] == best) {
                #pragma unroll
                for (int p = 0; p < 7; ++p) t[p] = t[p + 1];
                t[7] = 0ull;
            }
        }

        float s = __uint_as_float((u32)(mykey >> 32));
        bool mask = s > 0.0f;
        if (lane < 8) {
            float4 bx = make_float4(0.f, 0.f, 0.f, 0.f);
            float fcls = 0.f;
            if (mask) {
                int pos  = (int)(mykey & 0xFFFFu);
                int flat = 0x7FFF - (int)((mykey >> 16) & 0x7FFFu);
                fcls = (float)(flat / KCAND);
                float4 gb = g_boxes[(size_t)bb * (NCLS * MAXPC) + pos];
                bx.x = clamp01(gb.x); bx.y = clamp01(gb.y);
                bx.z = clamp01(gb.z); bx.w = clamp01(gb.w);
            }
            int ob = (bb * 8 + lane) * 4;
            out[ob + 0] = bx.x; out[ob + 1] = bx.y;
            out[ob + 2] = bx.z; out[ob + 3] = bx.w;
            out[NB * 8 * 4 + bb * 8 + lane]          = mask ? s : 0.f;    // scores  @256
            out[NB * 8 * 4 + NB * 8 + bb * 8 + lane] = mask ? fcls : 0.f; // classes @320
        }
        u32 vb = __ballot_sync(FULLM, (lane < 8) && mask);
        if (lane == 0)
            out[NB * 8 * 4 + 2 * NB * 8 + bb] = (float)__popc(vb);        // valid @384
    }
}

// ---------------------------------------------------------------------------
extern "C" void kernel_launch(void* const* d_in, const int* in_sizes, int n_in,
                              void* d_out, int out_size)
{
    const float* boxes  = (const float*)d_in[0];
    const float* scores = (const float*)d_in[1];
    int nbox = in_sizes[0] / (NB * 4);
    int nchunks = (nbox + CHUNK - 1) / CHUNK;
    int force_fb = (nbox > 32767) ? 1 : 0;   // u32 packing needs idx < 2^15

    scan_kernel<<<NB * nchunks, 256>>>(scores, nbox, nchunks);
    nms_kernel<<<NCLASSES / WPB, 32 * WPB>>>((const float4*)boxes, scores,
                                             (float*)d_out, nbox, force_fb);
}

// round 11
// speedup vs baseline: 1.0182x; 1.0182x over previous
#include <cuda_runtime.h>

typedef unsigned long long u64;
typedef unsigned int u32;

#define NB        8
#define NCLS      80
#define NCLASSES  (NB * NCLS)      // 640
#define KCAND     256
#define MAXPC     8
#define CSTRIDE32 1280             // u32 slots per class (= 640 u64 fallback view)
#define CAPSC     128              // trusted capture bound (E=64, sigma=8)
#define KRC       4                // u32 keys/lane = 128 sorted slots
#define KRF       20               // u64 keys/lane, fallback
#define LOCCAP    8
#define CHUNK     256
#define THR       0.9968f          // E[captures/class] = 64
#define SBASE     0x3F7F0000u
#define WPB       5                // warps per NMS CTA -> grid 128
#define NBUCKETS  1024
#define BATCH     16
#define FULLM     0xFFFFFFFFu

static __device__ u32    g_cand[NCLASSES * CSTRIDE32];  // 3.3 MB scratch
static __device__ int    g_cnt[NCLASSES];
static __device__ u64    g_keys[NCLASSES * MAXPC];
static __device__ float4 g_boxes[NCLASSES * MAXPC];
static __device__ u32    g_done;

__device__ __forceinline__ float clamp01(float x) { return fminf(fmaxf(x, 0.0f), 1.0f); }

__device__ __forceinline__ u64 warpmax64(u64 v)
{
    u32 hi = (u32)(v >> 32);
    u32 hmax = __reduce_max_sync(FULLM, hi);
    u32 lo = (hi == hmax) ? (u32)v : 0u;
    u32 lmax = __reduce_max_sync(FULLM, lo);
    return ((u64)hmax << 32) | lmax;
}

// ---------------------------------------------------------------------------
// Common path: bitonic-sort 128 u32 keys in registers, then greedy NMS in
// exact rank order with zero REDUX on the critical path.
// Returns kept count; *ranout true iff we exit without 8 keeps (pop cap 256
// is unreachable with <=128 candidates, so any shortfall needs the fallback).
// ---------------------------------------------------------------------------
__device__ int nms_sorted(const float4* __restrict__ boxes4, int nbox, int b, int c,
                          const u32* __restrict__ cand, int cnt, bool* ranout)
{
    const int lane = threadIdx.x & 31;

    u32 kr[KRC];
    #pragma unroll
    for (int r = 0; r < KRC; ++r) {
        int slot = r * 32 + lane;
        kr[r] = (slot < cnt) ? cand[slot] : 0u;
    }

    // ---- bitonic sort, 128 elements, descending; element e = lane + 32*r ----
    #pragma unroll
    for (int size = 2; size <= 128; size <<= 1) {
        #pragma unroll
        for (int stride = size >> 1; stride > 0; stride >>= 1) {
            if (stride >= 32) {
                const int rs = stride >> 5;       // 1 or 2
                #pragma unroll
                for (int r = 0; r < KRC; ++r) {
                    if ((r & rs) == 0) {
                        const int r2 = r | rs;
                        const int e = lane + 32 * r;
                        const bool descB = ((e & size) == 0);
                        u32 a = kr[r], d = kr[r2];
                        u32 mx = a > d ? a : d, mn = a > d ? d : a;
                        kr[r]  = descB ? mx : mn;
                        kr[r2] = descB ? mn : mx;
                    }
                }
            } else {
                #pragma unroll
                for (int r = 0; r < KRC; ++r) {
                    const int e = lane + 32 * r;
                    u32 other = __shfl_xor_sync(FULLM, kr[r], stride);
                    const bool iLow  = (lane & stride) == 0;
                    const bool descB = ((e & size) == 0);
                    const bool keepMax = (iLow == descB);
                    u32 mx = kr[r] > other ? kr[r] : other;
                    u32 mn = kr[r] > other ? other : kr[r];
                    kr[r] = keepMax ? mx : mn;
                }
            }
        }
    }
    // sorted: rank g*32 + lane lives in kr[g] at this lane

    float4 mykept = make_float4(0.f, 0.f, 0.f, 0.f);
    float  myka   = 0.f;
    int kc = 0;
    bool done = false;   // zero key seen or 8 keeps reached

    for (int g = 0; g < KRC && !done; ++g) {
        u32 kg = kr[g];
        // gather this rank-group's boxes in one parallel shot (MLP up to 32)
        float4 obox = make_float4(0.f, 0.f, 0.f, 0.f);
        if (kg) {
            u32 bi = 0x7FFFu - (kg & 0x7FFFu);
            obox = boxes4[(size_t)b * nbox + bi];
        }
        for (int r = 0; r < 32; ++r) {
            u32 key = __shfl_sync(FULLM, kg, r);          // uniform
            if (key == 0u) { done = true; break; }        // uniform
            float4 bx;
            bx.x = __shfl_sync(FULLM, obox.x, r);
            bx.y = __shfl_sync(FULLM, obox.y, r);
            bx.z = __shfl_sync(FULLM, obox.z, r);
            bx.w = __shfl_sync(FULLM, obox.w, r);
            float area = fmaxf(bx.z - bx.x, 0.f) * fmaxf(bx.w - bx.y, 0.f);

            bool supme = false;
            if (lane < kc) {
                float iy1 = fmaxf(bx.x, mykept.x), ix1 = fmaxf(bx.y, mykept.y);
                float iy2 = fminf(bx.z, mykept.z), ix2 = fminf(bx.w, mykept.w);
                float inter = fmaxf(iy2 - iy1, 0.f) * fmaxf(ix2 - ix1, 0.f);
                float uni = area + myka - inter;
                float iou = (uni > 0.f) ? inter / uni : 0.f;
                supme = iou > 0.5f;
            }
            bool keep = (__ballot_sync(FULLM, supme) == 0u);   // uniform

            if (keep) {
                if (lane == kc) {
                    mykept = bx;
                    myka = area;
                    int flat = c * KCAND + g * 32 + r;   // pop index = sorted rank
                    int pos  = c * MAXPC + kc;
                    g_keys[b * NCLS * MAXPC + pos] =
                        ((u64)((key >> 15) + SBASE) << 32) |
                        ((u64)(u32)(0x7FFF - flat) << 16) | (u32)pos;
                    g_boxes[b * NCLS * MAXPC + pos] = bx;
                }
                ++kc;
                if (kc >= MAXPC) { done = true; break; }  // REQUIRED (R10 bug)
            }
        }
    }
    *ranout = (kc < MAXPC);   // <=128 pops can never hit the 256 cap legitimately
    return kc;
}

// ---------------------------------------------------------------------------
// Fallback path (u64 keys, REDUX pops) — exact, never expected.
// ---------------------------------------------------------------------------
__device__ int run_nms_fb(const float4* __restrict__ boxes4, int nbox, int b, int c,
                          const u64* __restrict__ cand, int cnt)
{
    const int lane = threadIdx.x & 31;

    u64 kr[KRF];
    #pragma unroll
    for (int r = 0; r < KRF; ++r) {
        int slot = r * 32 + lane;
        kr[r] = (slot < cnt) ? cand[slot] : 0ull;
    }
    u64 mymax = kr[0];
    #pragma unroll
    for (int r = 1; r < KRF; ++r) if (kr[r] > mymax) mymax = kr[r];

    float4 mykept = make_float4(0.f, 0.f, 0.f, 0.f);
    float  myka   = 0.f;
    int kc = 0, totpops = 0;
    bool more = true;

    while (more && kc < MAXPC && totpops < KCAND) {
        const int lim = min(BATCH, KCAND - totpops);
        u64 okey = 0ull;
        int n = 0;
        for (int r = 0; r < lim; ++r) {
            u64 best = warpmax64(mymax);
            if ((u32)(best >> 32) <= 0x3F000000u) break;
            if (lane == r) okey = best;
            if (mymax == best) {
                mymax = 0ull;
                #pragma unroll
                for (int q = 0; q < KRF; ++q) {
                    if (kr[q] == best) kr[q] = 0ull;
                    if (kr[q] > mymax) mymax = kr[q];
                }
            }
            ++n;
        }
        more = (n == lim) && (lim == BATCH);

        float4 obox = make_float4(0.f, 0.f, 0.f, 0.f);
        if (lane < n)
            obox = boxes4[(size_t)b * nbox + (0xFFFFFFFFu - (u32)okey)];

        for (int r = 0; r < n; ++r) {
            float4 bx;
            bx.x = __shfl_sync(FULLM, obox.x, r);
            bx.y = __shfl_sync(FULLM, obox.y, r);
            bx.z = __shfl_sync(FULLM, obox.z, r);
            bx.w = __shfl_sync(FULLM, obox.w, r);
            u64 key = __shfl_sync(FULLM, okey, r);
            float area = fmaxf(bx.z - bx.x, 0.f) * fmaxf(bx.w - bx.y, 0.f);

            bool supme = false;
            if (lane < kc) {
                float iy1 = fmaxf(bx.x, mykept.x), ix1 = fmaxf(bx.y, mykept.y);
                float iy2 = fminf(bx.z, mykept.z), ix2 = fminf(bx.w, mykept.w);
                float inter = fmaxf(iy2 - iy1, 0.f) * fmaxf(ix2 - ix1, 0.f);
                float uni = area + myka - inter;
                float iou = (uni > 0.f) ? inter / uni : 0.f;
                supme = iou > 0.5f;
            }
            bool keep = (__ballot_sync(FULLM, supme) == 0u);

            if (keep) {
                if (lane == kc) {
                    mykept = bx; myka = area;
                    int flat = c * KCAND + totpops + r;
                    int pos  = c * MAXPC + kc;
                    g_keys[b * NCLS * MAXPC + pos] =
                        ((u64)(u32)(key >> 32) << 32) |
                        ((u64)(u32)(0x7FFF - flat) << 16) | (u32)pos;
                    g_boxes[b * NCLS * MAXPC + pos] = bx;
                }
                ++kc;
                if (kc >= MAXPC) return kc;
            }
        }
        totpops += n;
    }
    return kc;
}

// ---------------------------------------------------------------------------
// Kernel A: coalesced MLP-4 scan; capture s >= THR as packed u32 keys.
// ---------------------------------------------------------------------------
__global__ __launch_bounds__(256) void scan_kernel(
    const float* __restrict__ scores, int nbox, int nchunks)
{
    const int tid  = threadIdx.x;
    const int b    = blockIdx.x / nchunks;
    const int ch   = blockIdx.x % nchunks;
    const int box0 = ch * CHUNK;
    const int boxN = min(CHUNK, nbox - box0);

    __shared__ u32 loc[NCLS * LOCCAP];
    __shared__ int lcnt[NCLS];

    for (int i = tid; i < NCLS; i += 256) lcnt[i] = 0;
    __syncthreads();

    if (boxN > 0) {
        const float4* sp = reinterpret_cast<const float4*>(scores) +
                           (size_t)(b * nbox + box0) * (NCLS / 4);
        const int nf4 = boxN * (NCLS / 4);
        for (int t0 = tid; t0 < nf4; t0 += 1024) {
            float4 v[4];
            #pragma unroll
            for (int u = 0; u < 4; ++u) {
                int t = t0 + u * 256;
                v[u] = (t < nf4) ? sp[t] : make_float4(0.f, 0.f, 0.f, 0.f);
            }
            #pragma unroll
            for (int u = 0; u < 4; ++u) {
                int t = t0 + u * 256;
                if (t >= nf4) break;
                int box = box0 + t / (NCLS / 4);
                int g   = t % (NCLS / 4);
                float sv[4] = {v[u].x, v[u].y, v[u].z, v[u].w};
                #pragma unroll
                for (int k = 0; k < 4; ++k) {
                    if (sv[k] >= THR) {
                        int c = g * 4 + k;
                        u32 key = ((__float_as_uint(sv[k]) - SBASE) << 15) |
                                  (u32)(0x7FFF - box);
                        int p = atomicAdd(&lcnt[c], 1);
                        if (p < LOCCAP) {
                            loc[c * LOCCAP + p] = key;
                        } else {
                            int q = atomicAdd(&g_cnt[b * NCLS + c], 1);
                            if (q < CAPSC)
                                g_cand[(size_t)(b * NCLS + c) * CSTRIDE32 + q] = key;
                        }
                    }
                }
            }
        }
    }
    __syncthreads();

    for (int c = tid; c < NCLS; c += 256) {
        int n = min(lcnt[c], LOCCAP);
        if (n > 0) {
            int base = atomicAdd(&g_cnt[b * NCLS + c], n);
            for (int j = 0; j < n; ++j) {
                int q = base + j;
                if (q < CAPSC)
                    g_cand[(size_t)(b * NCLS + c) * CSTRIDE32 + q] = loc[c * LOCCAP + j];
            }
        }
    }
}

// ---------------------------------------------------------------------------
// Kernel B: one warp per (batch,class); sort-based NMS + fused finisher.
// ---------------------------------------------------------------------------
__global__ __launch_bounds__(32 * WPB) void nms_kernel(
    const float4* __restrict__ boxes4,
    const float*  __restrict__ scores,
    float* __restrict__ out,
    int nbox, int force_fb)
{
    const int tid  = threadIdx.x;
    const int lane = tid & 31;
    const int wid  = tid >> 5;
    const int cls  = blockIdx.x * WPB + wid;
    const int b    = cls / NCLS;
    const int c    = cls % NCLS;

    __shared__ u32 sh_hist[WPB][NBUCKETS];
    __shared__ int sh_fc[WPB];
    __shared__ int sh_last;

    const u32* cand32 = g_cand + (size_t)cls * CSTRIDE32;
    int cnt = g_cnt[cls];
    int kc = 0;
    bool needfb = force_fb || (cnt > CAPSC) || (cnt <= 0);

    if (!needfb) {
        bool ranout = false;
        kc = nms_sorted(boxes4, nbox, b, c, cand32, cnt, &ranout);
        needfb = ranout;
    }

    if (needfb) {
        // exact histogram rescan (never expected)
        u64* cand64 = (u64*)cand32;
        u32* hist = sh_hist[wid];
        for (int i = lane; i < NBUCKETS; i += 32) hist[i] = 0;
        __syncwarp();
        for (int i = lane; i < nbox; i += 32) {
            float s = scores[((size_t)b * nbox + i) * NCLS + c];
            atomicAdd(&hist[min((int)(s * (float)NBUCKETS), NBUCKETS - 1)], 1u);
        }
        __syncwarp();
        const int base = lane * 32;
        u32 part = 0;
        #pragma unroll
        for (int j = 0; j < 32; ++j) part += hist[base + j];
        u32 suf = part;
        #pragma unroll
        for (int off = 16; off; off >>= 1) {
            u32 v = __shfl_down_sync(FULLM, suf, off);
            if (lane + off < 32) suf += v;
        }
        u32 above = __shfl_down_sync(FULLM, suf, 1);
        if (lane == 31) above = 0;
        int T = -1;
        u32 prev = above;
        for (int bkt = base + 31; bkt >= base; --bkt) {
            u32 cur = prev + hist[bkt];
            if (cur >= KCAND && prev < KCAND) T = bkt;
            prev = cur;
        }
        #pragma unroll
        for (int off = 16; off; off >>= 1)
            T = max(T, __shfl_xor_sync(FULLM, T, off));
        T = max(T, 0);
        if (lane == 0) sh_fc[wid] = 0;
        __syncwarp();
        for (int i = lane; i < nbox; i += 32) {
            float s = scores[((size_t)b * nbox + i) * NCLS + c];
            int bk = min((int)(s * (float)NBUCKETS), NBUCKETS - 1);
            if (bk >= T) {
                int q = atomicAdd(&sh_fc[wid], 1);
                if (q < KRF * 32)
                    cand64[q] = ((u64)__float_as_uint(s) << 32) |
                                (u32)(0xFFFFFFFFu - (u32)i);
            }
        }
        __threadfence();
        __syncwarp();
        int fcnt = min(sh_fc[wid], KRF * 32);
        kc = run_nms_fb(boxes4, nbox, b, c, cand64, fcnt);
    }

    if (lane >= kc && lane < MAXPC)
        g_keys[(size_t)cls * MAXPC + lane] = 0ull;

    // ---- fused finisher: last CTA does per-batch top-8 + counter reset ----
    __syncthreads();
    if (tid == 0) {
        __threadfence();
        sh_last = (atomicAdd(&g_done, 1u) == (u32)(gridDim.x - 1));
    }
    __syncthreads();
    if (!sh_last) return;
    if (tid == 0) g_done = 0u;
    for (int i = tid; i < NCLASSES; i += 32 * WPB) g_cnt[i] = 0;
    __threadfence();

    for (int bb = wid; bb < NB; bb += WPB) {
        u64 t[8] = {0, 0, 0, 0, 0, 0, 0, 0};
        #pragma unroll
        for (int j = 0; j < 20; ++j) {
            u64 k = g_keys[(size_t)bb * (NCLS * MAXPC) + j * 32 + lane];
            if (k > t[7]) {
                #pragma unroll
                for (int p = 0; p < 8; ++p)
                    if (k > t[p]) { u64 tmp = t[p]; t[p] = k; k = tmp; }
            }
        }

        u64 mykey = 0ull;
        #pragma unroll
        for (int r = 0; r < 8; ++r) {
            u64 best = warpmax64(t[0]);
            if (lane == r) mykey = best;
            if (t[0] == best) {
                #pragma unroll
                for (int p = 0; p < 7; ++p) t[p] = t[p + 1];
                t[7] = 0ull;
            }
        }

        float s = __uint_as_float((u32)(mykey >> 32));
        bool mask = s > 0.0f;
        if (lane < 8) {
            float4 bx = make_float4(0.f, 0.f, 0.f, 0.f);
            float fcls = 0.f;
            if (mask) {
                int pos  = (int)(mykey & 0xFFFFu);
                int flat = 0x7FFF - (int)((mykey >> 16) & 0x7FFFu);
                fcls = (float)(flat / KCAND);
                float4 gb = g_boxes[(size_t)bb * (NCLS * MAXPC) + pos];
                bx.x = clamp01(gb.x); bx.y = clamp01(gb.y);
                bx.z = clamp01(gb.z); bx.w = clamp01(gb.w);
            }
            int ob = (bb * 8 + lane) * 4;
            out[ob + 0] = bx.x; out[ob + 1] = bx.y;
            out[ob + 2] = bx.z; out[ob + 3] = bx.w;
            out[NB * 8 * 4 + bb * 8 + lane]          = mask ? s : 0.f;
            out[NB * 8 * 4 + NB * 8 + bb * 8 + lane] = mask ? fcls : 0.f;
        }
        u32 vb = __ballot_sync(FULLM, (lane < 8) && mask);
        if (lane == 0)
            out[NB * 8 * 4 + 2 * NB * 8 + bb] = (float)__popc(vb);
    }
}

// ---------------------------------------------------------------------------
extern "C" void kernel_launch(void* const* d_in, const int* in_sizes, int n_in,
                              void* d_out, int out_size)
{
    const float* boxes  = (const float*)d_in[0];
    const float* scores = (const float*)d_in[1];
    int nbox = in_sizes[0] / (NB * 4);
    int nchunks = (nbox + CHUNK - 1) / CHUNK;
    int force_fb = (nbox > 32767) ? 1 : 0;

    scan_kernel<<<NB * nchunks, 256>>>(scores, nbox, nchunks);
    nms_kernel<<<NCLASSES / WPB, 32 * WPB>>>((const float4*)boxes, scores,
                                             (float*)d_out, nbox, force_fb);
}

// round 12
// speedup vs baseline: 1.0523x; 1.0336x over previous
#include <cuda_runtime.h>

typedef unsigned long long u64;
typedef unsigned int u32;

#define NB        8
#define NCLS      80
#define NCLASSES  (NB * NCLS)      // 640
#define KCAND     256
#define MAXPC     8
#define CSTRIDE32 1280             // u32 slots per class (= 640 u64 fallback view)
#define CAPSC     128              // trusted capture bound (E=64, sigma=8)
#define KRC       4                // u32 keys/lane = 128 sorted slots
#define KRF       20               // u64 keys/lane, fallback
#define LOCCAP    8
#define NCHUNKS   53               // grid = 8*53 = 424 <= 4 CTAs/SM * 148 SMs
#define THR       0.9968f          // E[captures/class] = 64
#define SBASE     0x3F7F0000u
#define NBUCKETS  1024
#define BATCH     16
#define FULLM     0xFFFFFFFFu

static __device__ u32    g_cand[NCLASSES * CSTRIDE32];  // 3.3 MB scratch
static __device__ int    g_cnt[NCLASSES];               // reset by CTA0 each launch
static __device__ u64    g_keys[NCLASSES * MAXPC];
static __device__ float4 g_boxes[NCLASSES * MAXPC];
static __device__ volatile u32 g_bar1, g_bar2;          // reset by CTA0 each launch

__device__ __forceinline__ float clamp01(float x) { return fminf(fmaxf(x, 0.0f), 1.0f); }

__device__ __forceinline__ u64 warpmax64(u64 v)
{
    u32 hi = (u32)(v >> 32);
    u32 hmax = __reduce_max_sync(FULLM, hi);
    u32 lo = (hi == hmax) ? (u32)v : 0u;
    u32 lmax = __reduce_max_sync(FULLM, lo);
    return ((u64)hmax << 32) | lmax;
}

// resident-grid software barrier (grid must be fully co-resident — guaranteed
// by __launch_bounds__(256,4) occupancy and grid=424 <= 592 capacity)
__device__ __forceinline__ void grid_barrier(volatile u32* bar, u32 target)
{
    __syncthreads();
    if (threadIdx.x == 0) {
        __threadfence();                       // release prior writes
        atomicAdd((u32*)bar, 1u);
        while (*bar < target) __nanosleep(64);
        __threadfence();                       // acquire
    }
    __syncthreads();
}

// ---------------------------------------------------------------------------
// Common path: bitonic-sort 128 u32 keys in registers, then greedy NMS in
// exact rank order. *ranout true iff exit without 8 keeps (<=128 pops can
// never legitimately hit the 256-pop cap, so any shortfall -> fallback).
// ---------------------------------------------------------------------------
__device__ int nms_sorted(const float4* __restrict__ boxes4, int nbox, int b, int c,
                          const u32* __restrict__ cand, int cnt, bool* ranout)
{
    const int lane = threadIdx.x & 31;

    u32 kr[KRC];
    #pragma unroll
    for (int r = 0; r < KRC; ++r) {
        int slot = r * 32 + lane;
        kr[r] = (slot < cnt) ? cand[slot] : 0u;
    }

    // bitonic sort, 128 elements, descending; element e = lane + 32*r
    #pragma unroll
    for (int size = 2; size <= 128; size <<= 1) {
        #pragma unroll
        for (int stride = size >> 1; stride > 0; stride >>= 1) {
            if (stride >= 32) {
                const int rs = stride >> 5;
                #pragma unroll
                for (int r = 0; r < KRC; ++r) {
                    if ((r & rs) == 0) {
                        const int r2 = r | rs;
                        const int e = lane + 32 * r;
                        const bool descB = ((e & size) == 0);
                        u32 a = kr[r], d = kr[r2];
                        u32 mx = a > d ? a : d, mn = a > d ? d : a;
                        kr[r]  = descB ? mx : mn;
                        kr[r2] = descB ? mn : mx;
                    }
                }
            } else {
                #pragma unroll
                for (int r = 0; r < KRC; ++r) {
                    const int e = lane + 32 * r;
                    u32 other = __shfl_xor_sync(FULLM, kr[r], stride);
                    const bool iLow  = (lane & stride) == 0;
                    const bool descB = ((e & size) == 0);
                    const bool keepMax = (iLow == descB);
                    u32 mx = kr[r] > other ? kr[r] : other;
                    u32 mn = kr[r] > other ? other : kr[r];
                    kr[r] = keepMax ? mx : mn;
                }
            }
        }
    }

    float4 mykept = make_float4(0.f, 0.f, 0.f, 0.f);
    float  myka   = 0.f;
    int kc = 0;
    bool done = false;

    for (int g = 0; g < KRC && !done; ++g) {
        u32 kg = kr[g];
        float4 obox = make_float4(0.f, 0.f, 0.f, 0.f);
        if (kg) {
            u32 bi = 0x7FFFu - (kg & 0x7FFFu);
            obox = boxes4[(size_t)b * nbox + bi];
        }
        for (int r = 0; r < 32; ++r) {
            u32 key = __shfl_sync(FULLM, kg, r);          // uniform
            if (key == 0u) { done = true; break; }        // uniform
            float4 bx;
            bx.x = __shfl_sync(FULLM, obox.x, r);
            bx.y = __shfl_sync(FULLM, obox.y, r);
            bx.z = __shfl_sync(FULLM, obox.z, r);
            bx.w = __shfl_sync(FULLM, obox.w, r);
            float area = fmaxf(bx.z - bx.x, 0.f) * fmaxf(bx.w - bx.y, 0.f);

            bool supme = false;
            if (lane < kc) {
                float iy1 = fmaxf(bx.x, mykept.x), ix1 = fmaxf(bx.y, mykept.y);
                float iy2 = fminf(bx.z, mykept.z), ix2 = fminf(bx.w, mykept.w);
                float inter = fmaxf(iy2 - iy1, 0.f) * fmaxf(ix2 - ix1, 0.f);
                float uni = area + myka - inter;
                float iou = (uni > 0.f) ? inter / uni : 0.f;
                supme = iou > 0.5f;
            }
            bool keep = (__ballot_sync(FULLM, supme) == 0u);   // uniform

            if (keep) {
                if (lane == kc) {
                    mykept = bx;
                    myka = area;
                    int flat = c * KCAND + g * 32 + r;
                    int pos  = c * MAXPC + kc;
                    g_keys[b * NCLS * MAXPC + pos] =
                        ((u64)((key >> 15) + SBASE) << 32) |
                        ((u64)(u32)(0x7FFF - flat) << 16) | (u32)pos;
                    g_boxes[b * NCLS * MAXPC + pos] = bx;
                }
                ++kc;
                if (kc >= MAXPC) { done = true; break; }  // uniform
            }
        }
    }
    *ranout = (kc < MAXPC);
    return kc;
}

// ---------------------------------------------------------------------------
// Fallback path (u64 keys, REDUX pops) — exact, never expected.
// ---------------------------------------------------------------------------
__device__ int run_nms_fb(const float4* __restrict__ boxes4, int nbox, int b, int c,
                          const u64* __restrict__ cand, int cnt)
{
    const int lane = threadIdx.x & 31;

    u64 kr[KRF];
    #pragma unroll
    for (int r = 0; r < KRF; ++r) {
        int slot = r * 32 + lane;
        kr[r] = (slot < cnt) ? cand[slot] : 0ull;
    }
    u64 mymax = kr[0];
    #pragma unroll
    for (int r = 1; r < KRF; ++r) if (kr[r] > mymax) mymax = kr[r];

    float4 mykept = make_float4(0.f, 0.f, 0.f, 0.f);
    float  myka   = 0.f;
    int kc = 0, totpops = 0;
    bool more = true;

    while (more && kc < MAXPC && totpops < KCAND) {
        const int lim = min(BATCH, KCAND - totpops);
        u64 okey = 0ull;
        int n = 0;
        for (int r = 0; r < lim; ++r) {
            u64 best = warpmax64(mymax);
            if ((u32)(best >> 32) <= 0x3F000000u) break;
            if (lane == r) okey = best;
            if (mymax == best) {
                mymax = 0ull;
                #pragma unroll
                for (int q = 0; q < KRF; ++q) {
                    if (kr[q] == best) kr[q] = 0ull;
                    if (kr[q] > mymax) mymax = kr[q];
                }
            }
            ++n;
        }
        more = (n == lim) && (lim == BATCH);

        float4 obox = make_float4(0.f, 0.f, 0.f, 0.f);
        if (lane < n)
            obox = boxes4[(size_t)b * nbox + (0xFFFFFFFFu - (u32)okey)];

        for (int r = 0; r < n; ++r) {
            float4 bx;
            bx.x = __shfl_sync(FULLM, obox.x, r);
            bx.y = __shfl_sync(FULLM, obox.y, r);
            bx.z = __shfl_sync(FULLM, obox.z, r);
            bx.w = __shfl_sync(FULLM, obox.w, r);
            u64 key = __shfl_sync(FULLM, okey, r);
            float area = fmaxf(bx.z - bx.x, 0.f) * fmaxf(bx.w - bx.y, 0.f);

            bool supme = false;
            if (lane < kc) {
                float iy1 = fmaxf(bx.x, mykept.x), ix1 = fmaxf(bx.y, mykept.y);
                float iy2 = fminf(bx.z, mykept.z), ix2 = fminf(bx.w, mykept.w);
                float inter = fmaxf(iy2 - iy1, 0.f) * fmaxf(ix2 - ix1, 0.f);
                float uni = area + myka - inter;
                float iou = (uni > 0.f) ? inter / uni : 0.f;
                supme = iou > 0.5f;
            }
            bool keep = (__ballot_sync(FULLM, supme) == 0u);

            if (keep) {
                if (lane == kc) {
                    mykept = bx; myka = area;
                    int flat = c * KCAND + totpops + r;
                    int pos  = c * MAXPC + kc;
                    g_keys[b * NCLS * MAXPC + pos] =
                        ((u64)(u32)(key >> 32) << 32) |
                        ((u64)(u32)(0x7FFF - flat) << 16) | (u32)pos;
                    g_boxes[b * NCLS * MAXPC + pos] = bx;
                }
                ++kc;
                if (kc >= MAXPC) return kc;
            }
        }
        totpops += n;
    }
    return kc;
}

// ---------------------------------------------------------------------------
// Fused kernel: scan -> grid barrier -> per-warp NMS -> grid barrier -> CTA0
// finisher + counter reset. 424 CTAs, all co-resident.
// ---------------------------------------------------------------------------
__global__ void __launch_bounds__(256, 4) fused_kernel(
    const float4* __restrict__ boxes4,
    const float*  __restrict__ scores,
    float* __restrict__ out,
    int nbox, int chunk, int force_fb)
{
    const int tid  = threadIdx.x;
    const int lane = tid & 31;
    const int wid  = tid >> 5;
    const u32 grid = gridDim.x;

    __shared__ u32 sh_loc[NCLS * LOCCAP];    // 2.5 KB (phase 1)
    __shared__ int sh_lcnt[NCLS];
    __shared__ u32 sh_hist[8][NBUCKETS];     // 32 KB (phase 2 fallback only)
    __shared__ int sh_fc[8];

    // ================= phase 1: coalesced MLP-4 scan =================
    {
        const int b    = blockIdx.x / NCHUNKS;
        const int ch   = blockIdx.x % NCHUNKS;
        const int box0 = ch * chunk;
        const int boxN = min(chunk, nbox - box0);

        for (int i = tid; i < NCLS; i += 256) sh_lcnt[i] = 0;
        __syncthreads();

        if (boxN > 0) {
            const float4* sp = reinterpret_cast<const float4*>(scores) +
                               (size_t)(b * nbox + box0) * (NCLS / 4);
            const int nf4 = boxN * (NCLS / 4);
            for (int t0 = tid; t0 < nf4; t0 += 1024) {
                float4 v[4];
                #pragma unroll
                for (int u = 0; u < 4; ++u) {
                    int t = t0 + u * 256;
                    v[u] = (t < nf4) ? sp[t] : make_float4(0.f, 0.f, 0.f, 0.f);
                }
                #pragma unroll
                for (int u = 0; u < 4; ++u) {
                    int t = t0 + u * 256;
                    if (t >= nf4) break;
                    int box = box0 + t / (NCLS / 4);
                    int g   = t % (NCLS / 4);
                    float sv[4] = {v[u].x, v[u].y, v[u].z, v[u].w};
                    #pragma unroll
                    for (int k = 0; k < 4; ++k) {
                        if (sv[k] >= THR) {
                            int c = g * 4 + k;
                            u32 key = ((__float_as_uint(sv[k]) - SBASE) << 15) |
                                      (u32)(0x7FFF - box);
                            int p = atomicAdd(&sh_lcnt[c], 1);
                            if (p < LOCCAP) {
                                sh_loc[c * LOCCAP + p] = key;
                            } else {  // rare spill (set stays complete)
                                int q = atomicAdd(&g_cnt[b * NCLS + c], 1);
                                if (q < CAPSC)
                                    g_cand[(size_t)(b * NCLS + c) * CSTRIDE32 + q] = key;
                            }
                        }
                    }
                }
            }
        }
        __syncthreads();

        for (int c = tid; c < NCLS; c += 256) {
            int n = min(sh_lcnt[c], LOCCAP);
            if (n > 0) {
                int base = atomicAdd(&g_cnt[b * NCLS + c], n);
                for (int j = 0; j < n; ++j) {
                    int q = base + j;
                    if (q < CAPSC)
                        g_cand[(size_t)(b * NCLS + c) * CSTRIDE32 + q] =
                            sh_loc[c * LOCCAP + j];
                }
            }
        }
    }

    grid_barrier(&g_bar1, grid);

    // ================= phase 2: per-warp NMS (first 640 warps) =================
    const int gw = blockIdx.x * 8 + wid;
    if (gw < NCLASSES) {
        const int cls = gw;
        const int b   = cls / NCLS;
        const int c   = cls % NCLS;
        const u32* cand32 = g_cand + (size_t)cls * CSTRIDE32;
        int cnt = g_cnt[cls];
        int kc = 0;
        bool needfb = force_fb || (cnt > CAPSC) || (cnt <= 0);

        if (!needfb) {
            bool ranout = false;
            kc = nms_sorted(boxes4, nbox, b, c, cand32, cnt, &ranout);
            needfb = ranout;
        }

        if (needfb) {
            // exact histogram rescan (never expected)
            u64* cand64 = (u64*)cand32;
            u32* hist = sh_hist[wid];
            for (int i = lane; i < NBUCKETS; i += 32) hist[i] = 0;
            __syncwarp();
            for (int i = lane; i < nbox; i += 32) {
                float s = scores[((size_t)b * nbox + i) * NCLS + c];
                atomicAdd(&hist[min((int)(s * (float)NBUCKETS), NBUCKETS - 1)], 1u);
            }
            __syncwarp();
            const int base = lane * 32;
            u32 part = 0;
            #pragma unroll
            for (int j = 0; j < 32; ++j) part += hist[base + j];
            u32 suf = part;
            #pragma unroll
            for (int off = 16; off; off >>= 1) {
                u32 v = __shfl_down_sync(FULLM, suf, off);
                if (lane + off < 32) suf += v;
            }
            u32 above = __shfl_down_sync(FULLM, suf, 1);
            if (lane == 31) above = 0;
            int T = -1;
            u32 prev = above;
            for (int bkt = base + 31; bkt >= base; --bkt) {
                u32 cur = prev + hist[bkt];
                if (cur >= KCAND && prev < KCAND) T = bkt;
                prev = cur;
            }
            #pragma unroll
            for (int off = 16; off; off >>= 1)
                T = max(T, __shfl_xor_sync(FULLM, T, off));
            T = max(T, 0);
            if (lane == 0) sh_fc[wid] = 0;
            __syncwarp();
            for (int i = lane; i < nbox; i += 32) {
                float s = scores[((size_t)b * nbox + i) * NCLS + c];
                int bk = min((int)(s * (float)NBUCKETS), NBUCKETS - 1);
                if (bk >= T) {
                    int q = atomicAdd(&sh_fc[wid], 1);
                    if (q < KRF * 32)
                        cand64[q] = ((u64)__float_as_uint(s) << 32) |
                                    (u32)(0xFFFFFFFFu - (u32)i);
                }
            }
            __threadfence();
            __syncwarp();
            int fcnt = min(sh_fc[wid], KRF * 32);
            kc = run_nms_fb(boxes4, nbox, b, c, cand64, fcnt);
        }

        if (lane >= kc && lane < MAXPC)
            g_keys[(size_t)cls * MAXPC + lane] = 0ull;
    }

    grid_barrier(&g_bar2, grid);

    if (blockIdx.x != 0) return;

    // ================= phase 3: CTA0 finisher (warp wid = batch wid) ==========
    {
        const int bb = wid;   // 8 warps == 8 batches
        u64 t[8] = {0, 0, 0, 0, 0, 0, 0, 0};
        #pragma unroll
        for (int j = 0; j < 20; ++j) {
            u64 k = g_keys[(size_t)bb * (NCLS * MAXPC) + j * 32 + lane];
            if (k > t[7]) {
                #pragma unroll
                for (int p = 0; p < 8; ++p)
                    if (k > t[p]) { u64 tmp = t[p]; t[p] = k; k = tmp; }
            }
        }

        u64 mykey = 0ull;
        #pragma unroll
        for (int r = 0; r < 8; ++r) {
            u64 best = warpmax64(t[0]);
            if (lane == r) mykey = best;
            if (t[0] == best) {
                #pragma unroll
                for (int p = 0; p < 7; ++p) t[p] = t[p + 1];
                t[7] = 0ull;
            }
        }

        float s = __uint_as_float((u32)(mykey >> 32));
        bool mask = s > 0.0f;
        if (lane < 8) {
            float4 bx = make_float4(0.f, 0.f, 0.f, 0.f);
            float fcls = 0.f;
            if (mask) {
                int pos  = (int)(mykey & 0xFFFFu);
                int flat = 0x7FFF - (int)((mykey >> 16) & 0x7FFFu);
                fcls = (float)(flat / KCAND);
                float4 gb = g_boxes[(size_t)bb * (NCLS * MAXPC) + pos];
                bx.x = clamp01(gb.x); bx.y = clamp01(gb.y);
                bx.z = clamp01(gb.z); bx.w = clamp01(gb.w);
            }
            int ob = (bb * 8 + lane) * 4;
            out[ob + 0] = bx.x; out[ob + 1] = bx.y;
            out[ob + 2] = bx.z; out[ob + 3] = bx.w;
            out[NB * 8 * 4 + bb * 8 + lane]          = mask ? s : 0.f;    // scores  @256
            out[NB * 8 * 4 + NB * 8 + bb * 8 + lane] = mask ? fcls : 0.f; // classes @320
        }
        u32 vb = __ballot_sync(FULLM, (lane < 8) && mask);
        if (lane == 0)
            out[NB * 8 * 4 + 2 * NB * 8 + bb] = (float)__popc(vb);        // valid @384
    }

    // reset scratch for the next graph replay (all phase-2 readers are past
    // barrier 2; kernel-boundary ordering covers the next launch)
    __syncthreads();
    if (tid == 0) { g_bar1 = 0; g_bar2 = 0; }
    for (int i = tid; i < NCLASSES; i += 256) g_cnt[i] = 0;
}

// ---------------------------------------------------------------------------
extern "C" void kernel_launch(void* const* d_in, const int* in_sizes, int n_in,
                              void* d_out, int out_size)
{
    const float* boxes  = (const float*)d_in[0];
    const float* scores = (const float*)d_in[1];
    int nbox = in_sizes[0] / (NB * 4);
    int chunk = (nbox + NCHUNKS - 1) / NCHUNKS;   // grid is FIXED at 424 CTAs
    int force_fb = (nbox > 32767) ? 1 : 0;

    fused_kernel<<<NB * NCHUNKS, 256>>>((const float4*)boxes, scores,
                                        (float*)d_out, nbox, chunk, force_fb);
}

// round 13
// speedup vs baseline: 1.1058x; 1.0508x over previous
#include <cuda_runtime.h>

typedef unsigned long long u64;
typedef unsigned int u32;

#define NB        8
#define NCLS      80
#define NCLASSES  (NB * NCLS)      // 640
#define KCAND     256
#define MAXPC     8
#define CSTRIDE32 1280             // u32 slots per class (= 640 u64 fallback view)
#define CAPSC     128              // trusted capture bound (E=64, sigma=8)
#define KRC       4                // u32 keys/lane = 128 sorted slots
#define KRF       20               // u64 keys/lane, fallback
#define LOCCAP    8
#define NCHUNKS   74               // grid = 8*74 = 592 = exactly 4 CTAs/SM * 148
#define THR       0.9968f          // E[captures/class] = 64
#define SBASE     0x3F7F0000u
#define NBUCKETS  1024
#define BATCH     16
#define FULLM     0xFFFFFFFFu

static __device__ u32    g_cand[NCLASSES * CSTRIDE32];  // 3.3 MB scratch
static __device__ int    g_cnt[NCLASSES];               // reset by CTA0 each launch
static __device__ u64    g_keys[NCLASSES * MAXPC];
static __device__ float4 g_boxes[NCLASSES * MAXPC];
static __device__ u32    g_hist[NCLASSES * NBUCKETS];   // fallback-only scratch (2.6 MB)
static __device__ volatile u32 g_bar1, g_bar2;          // reset by CTA0 each launch

__device__ __forceinline__ float clamp01(float x) { return fminf(fmaxf(x, 0.0f), 1.0f); }

__device__ __forceinline__ u64 warpmax64(u64 v)
{
    u32 hi = (u32)(v >> 32);
    u32 hmax = __reduce_max_sync(FULLM, hi);
    u32 lo = (hi == hmax) ? (u32)v : 0u;
    u32 lmax = __reduce_max_sync(FULLM, lo);
    return ((u64)hmax << 32) | lmax;
}

// resident-grid software barrier (co-residency guaranteed: launch_bounds(256,4),
// grid = 592 = 4 * 148)
__device__ __forceinline__ void grid_barrier(volatile u32* bar, u32 target)
{
    __syncthreads();
    if (threadIdx.x == 0) {
        __threadfence();
        atomicAdd((u32*)bar, 1u);
        while (*bar < target) __nanosleep(64);
        __threadfence();
    }
    __syncthreads();
}

// ---------------------------------------------------------------------------
// Common path: bitonic-sort 128 u32 keys in registers, then greedy NMS in
// exact rank order. *ranout true iff exit without 8 keeps.
// ---------------------------------------------------------------------------
__device__ int nms_sorted(const float4* __restrict__ boxes4, int nbox, int b, int c,
                          const u32* __restrict__ cand, int cnt, bool* ranout)
{
    const int lane = threadIdx.x & 31;

    u32 kr[KRC];
    #pragma unroll
    for (int r = 0; r < KRC; ++r) {
        int slot = r * 32 + lane;
        kr[r] = (slot < cnt) ? cand[slot] : 0u;
    }

    // bitonic sort, 128 elements, descending; element e = lane + 32*r
    #pragma unroll
    for (int size = 2; size <= 128; size <<= 1) {
        #pragma unroll
        for (int stride = size >> 1; stride > 0; stride >>= 1) {
            if (stride >= 32) {
                const int rs = stride >> 5;
                #pragma unroll
                for (int r = 0; r < KRC; ++r) {
                    if ((r & rs) == 0) {
                        const int r2 = r | rs;
                        const int e = lane + 32 * r;
                        const bool descB = ((e & size) == 0);
                        u32 a = kr[r], d = kr[r2];
                        u32 mx = a > d ? a : d, mn = a > d ? d : a;
                        kr[r]  = descB ? mx : mn;
                        kr[r2] = descB ? mn : mx;
                    }
                }
            } else {
                #pragma unroll
                for (int r = 0; r < KRC; ++r) {
                    const int e = lane + 32 * r;
                    u32 other = __shfl_xor_sync(FULLM, kr[r], stride);
                    const bool iLow  = (lane & stride) == 0;
                    const bool descB = ((e & size) == 0);
                    const bool keepMax = (iLow == descB);
                    u32 mx = kr[r] > other ? kr[r] : other;
                    u32 mn = kr[r] > other ? other : kr[r];
                    kr[r] = keepMax ? mx : mn;
                }
            }
        }
    }

    float4 mykept = make_float4(0.f, 0.f, 0.f, 0.f);
    float  myka   = 0.f;
    int kc = 0;
    bool done = false;

    for (int g = 0; g < KRC && !done; ++g) {
        u32 kg = kr[g];
        float4 obox = make_float4(0.f, 0.f, 0.f, 0.f);
        if (kg) {
            u32 bi = 0x7FFFu - (kg & 0x7FFFu);
            obox = boxes4[(size_t)b * nbox + bi];
        }
        for (int r = 0; r < 32; ++r) {
            u32 key = __shfl_sync(FULLM, kg, r);          // uniform
            if (key == 0u) { done = true; break; }        // uniform
            float4 bx;
            bx.x = __shfl_sync(FULLM, obox.x, r);
            bx.y = __shfl_sync(FULLM, obox.y, r);
            bx.z = __shfl_sync(FULLM, obox.z, r);
            bx.w = __shfl_sync(FULLM, obox.w, r);
            float area = fmaxf(bx.z - bx.x, 0.f) * fmaxf(bx.w - bx.y, 0.f);

            bool supme = false;
            if (lane < kc) {
                float iy1 = fmaxf(bx.x, mykept.x), ix1 = fmaxf(bx.y, mykept.y);
                float iy2 = fminf(bx.z, mykept.z), ix2 = fminf(bx.w, mykept.w);
                float inter = fmaxf(iy2 - iy1, 0.f) * fmaxf(ix2 - ix1, 0.f);
                float uni = area + myka - inter;
                float iou = (uni > 0.f) ? inter / uni : 0.f;
                supme = iou > 0.5f;
            }
            bool keep = (__ballot_sync(FULLM, supme) == 0u);   // uniform

            if (keep) {
                if (lane == kc) {
                    mykept = bx;
                    myka = area;
                    int flat = c * KCAND + g * 32 + r;
                    int pos  = c * MAXPC + kc;
                    g_keys[b * NCLS * MAXPC + pos] =
                        ((u64)((key >> 15) + SBASE) << 32) |
                        ((u64)(u32)(0x7FFF - flat) << 16) | (u32)pos;
                    g_boxes[b * NCLS * MAXPC + pos] = bx;
                }
                ++kc;
                if (kc >= MAXPC) { done = true; break; }  // uniform
            }
        }
    }
    *ranout = (kc < MAXPC);
    return kc;
}

// ---------------------------------------------------------------------------
// Fallback path (u64 keys, REDUX pops) — exact, never expected.
// ---------------------------------------------------------------------------
__device__ int run_nms_fb(const float4* __restrict__ boxes4, int nbox, int b, int c,
                          const u64* __restrict__ cand, int cnt)
{
    const int lane = threadIdx.x & 31;

    u64 kr[KRF];
    #pragma unroll
    for (int r = 0; r < KRF; ++r) {
        int slot = r * 32 + lane;
        kr[r] = (slot < cnt) ? cand[slot] : 0ull;
    }
    u64 mymax = kr[0];
    #pragma unroll
    for (int r = 1; r < KRF; ++r) if (kr[r] > mymax) mymax = kr[r];

    float4 mykept = make_float4(0.f, 0.f, 0.f, 0.f);
    float  myka   = 0.f;
    int kc = 0, totpops = 0;
    bool more = true;

    while (more && kc < MAXPC && totpops < KCAND) {
        const int lim = min(BATCH, KCAND - totpops);
        u64 okey = 0ull;
        int n = 0;
        for (int r = 0; r < lim; ++r) {
            u64 best = warpmax64(mymax);
            if ((u32)(best >> 32) <= 0x3F000000u) break;
            if (lane == r) okey = best;
            if (mymax == best) {
                mymax = 0ull;
                #pragma unroll
                for (int q = 0; q < KRF; ++q) {
                    if (kr[q] == best) kr[q] = 0ull;
                    if (kr[q] > mymax) mymax = kr[q];
                }
            }
            ++n;
        }
        more = (n == lim) && (lim == BATCH);

        float4 obox = make_float4(0.f, 0.f, 0.f, 0.f);
        if (lane < n)
            obox = boxes4[(size_t)b * nbox + (0xFFFFFFFFu - (u32)okey)];

        for (int r = 0; r < n; ++r) {
            float4 bx;
            bx.x = __shfl_sync(FULLM, obox.x, r);
            bx.y = __shfl_sync(FULLM, obox.y, r);
            bx.z = __shfl_sync(FULLM, obox.z, r);
            bx.w = __shfl_sync(FULLM, obox.w, r);
            u64 key = __shfl_sync(FULLM, okey, r);
            float area = fmaxf(bx.z - bx.x, 0.f) * fmaxf(bx.w - bx.y, 0.f);

            bool supme = false;
            if (lane < kc) {
                float iy1 = fmaxf(bx.x, mykept.x), ix1 = fmaxf(bx.y, mykept.y);
                float iy2 = fminf(bx.z, mykept.z), ix2 = fminf(bx.w, mykept.w);
                float inter = fmaxf(iy2 - iy1, 0.f) * fmaxf(ix2 - ix1, 0.f);
                float uni = area + myka - inter;
                float iou = (uni > 0.f) ? inter / uni : 0.f;
                supme = iou > 0.5f;
            }
            bool keep = (__ballot_sync(FULLM, supme) == 0u);

            if (keep) {
                if (lane == kc) {
                    mykept = bx; myka = area;
                    int flat = c * KCAND + totpops + r;
                    int pos  = c * MAXPC + kc;
                    g_keys[b * NCLS * MAXPC + pos] =
                        ((u64)(u32)(key >> 32) << 32) |
                        ((u64)(u32)(0x7FFF - flat) << 16) | (u32)pos;
                    g_boxes[b * NCLS * MAXPC + pos] = bx;
                }
                ++kc;
                if (kc >= MAXPC) return kc;
            }
        }
        totpops += n;
    }
    return kc;
}

// ---------------------------------------------------------------------------
// Fused kernel: scan -> grid barrier -> per-warp NMS -> grid barrier -> CTA0
// finisher + counter reset. 592 CTAs, all co-resident (4/SM exactly).
// ---------------------------------------------------------------------------
__global__ void __launch_bounds__(256, 4) fused_kernel(
    const float4* __restrict__ boxes4,
    const float*  __restrict__ scores,
    float* __restrict__ out,
    int nbox, int chunk, int force_fb)
{
    const int tid  = threadIdx.x;
    const int lane = tid & 31;
    const int wid  = tid >> 5;
    const u32 grid = gridDim.x;

    __shared__ u32 sh_loc[NCLS * LOCCAP];    // 2.5 KB
    __shared__ int sh_lcnt[NCLS];
    __shared__ int sh_fc[8];

    // ================= phase 1: coalesced scan with fast-reject ==============
    {
        const int b    = blockIdx.x / NCHUNKS;
        const int ch   = blockIdx.x % NCHUNKS;
        const int box0 = ch * chunk;
        const int boxN = min(chunk, nbox - box0);

        for (int i = tid; i < NCLS; i += 256) sh_lcnt[i] = 0;
        __syncthreads();

        if (boxN > 0) {
            const float4* sp = reinterpret_cast<const float4*>(scores) +
                               (size_t)(b * nbox + box0) * (NCLS / 4);
            const int nf4 = boxN * (NCLS / 4);
            for (int t0 = tid; t0 < nf4; t0 += 1024) {
                float4 v[4];
                #pragma unroll
                for (int u = 0; u < 4; ++u) {
                    int t = t0 + u * 256;
                    v[u] = (t < nf4) ? sp[t] : make_float4(0.f, 0.f, 0.f, 0.f);
                }
                #pragma unroll
                for (int u = 0; u < 4; ++u) {
                    // fast reject: 3 FMAX + 1 compare for 4 scores (common path)
                    float m = fmaxf(fmaxf(v[u].x, v[u].y), fmaxf(v[u].z, v[u].w));
                    if (m >= THR) {   // rare (~1.3% of float4s)
                        int t = t0 + u * 256;
                        int box = box0 + t / (NCLS / 4);
                        int g   = t % (NCLS / 4);
                        float sv[4] = {v[u].x, v[u].y, v[u].z, v[u].w};
                        #pragma unroll
                        for (int k = 0; k < 4; ++k) {
                            if (sv[k] >= THR) {
                                int c = g * 4 + k;
                                u32 key = ((__float_as_uint(sv[k]) - SBASE) << 15) |
                                          (u32)(0x7FFF - box);
                                int p = atomicAdd(&sh_lcnt[c], 1);
                                if (p < LOCCAP) {
                                    sh_loc[c * LOCCAP + p] = key;
                                } else {  // rare spill (set stays complete)
                                    int q = atomicAdd(&g_cnt[b * NCLS + c], 1);
                                    if (q < CAPSC)
                                        g_cand[(size_t)(b * NCLS + c) * CSTRIDE32 + q] = key;
                                }
                            }
                        }
                    }
                }
            }
        }
        __syncthreads();

        for (int c = tid; c < NCLS; c += 256) {
            int n = min(sh_lcnt[c], LOCCAP);
            if (n > 0) {
                int base = atomicAdd(&g_cnt[b * NCLS + c], n);
                for (int j = 0; j < n; ++j) {
                    int q = base + j;
                    if (q < CAPSC)
                        g_cand[(size_t)(b * NCLS + c) * CSTRIDE32 + q] =
                            sh_loc[c * LOCCAP + j];
                }
            }
        }
    }

    grid_barrier(&g_bar1, grid);

    // ================= phase 2: per-warp NMS (first 640 warps) ===============
    const int gw = blockIdx.x * 8 + wid;
    if (gw < NCLASSES) {
        const int cls = gw;
        const int b   = cls / NCLS;
        const int c   = cls % NCLS;
        const u32* cand32 = g_cand + (size_t)cls * CSTRIDE32;
        int cnt = g_cnt[cls];
        int kc = 0;
        bool needfb = force_fb || (cnt > CAPSC) || (cnt <= 0);

        if (!needfb) {
            bool ranout = false;
            kc = nms_sorted(boxes4, nbox, b, c, cand32, cnt, &ranout);
            needfb = ranout;
        }

        if (needfb) {
            // exact histogram rescan in GLOBAL scratch (never expected)
            u64* cand64 = (u64*)cand32;
            u32* hist = g_hist + (size_t)cls * NBUCKETS;
            for (int i = lane; i < NBUCKETS; i += 32) hist[i] = 0;
            __syncwarp();
            for (int i = lane; i < nbox; i += 32) {
                float s = scores[((size_t)b * nbox + i) * NCLS + c];
                atomicAdd(&hist[min((int)(s * (float)NBUCKETS), NBUCKETS - 1)], 1u);
            }
            __syncwarp();
            const int base = lane * 32;
            u32 part = 0;
            #pragma unroll
            for (int j = 0; j < 32; ++j) part += hist[base + j];
            u32 suf = part;
            #pragma unroll
            for (int off = 16; off; off >>= 1) {
                u32 v = __shfl_down_sync(FULLM, suf, off);
                if (lane + off < 32) suf += v;
            }
            u32 above = __shfl_down_sync(FULLM, suf, 1);
            if (lane == 31) above = 0;
            int T = -1;
            u32 prev = above;
            for (int bkt = base + 31; bkt >= base; --bkt) {
                u32 cur = prev + hist[bkt];
                if (cur >= KCAND && prev < KCAND) T = bkt;
                prev = cur;
            }
            #pragma unroll
            for (int off = 16; off; off >>= 1)
                T = max(T, __shfl_xor_sync(FULLM, T, off));
            T = max(T, 0);
            if (lane == 0) sh_fc[wid] = 0;
            __syncwarp();
            for (int i = lane; i < nbox; i += 32) {
                float s = scores[((size_t)b * nbox + i) * NCLS + c];
                int bk = min((int)(s * (float)NBUCKETS), NBUCKETS - 1);
                if (bk >= T) {
                    int q = atomicAdd(&sh_fc[wid], 1);
                    if (q < KRF * 32)
                        cand64[q] = ((u64)__float_as_uint(s) << 32) |
                                    (u32)(0xFFFFFFFFu - (u32)i);
                }
            }
            __threadfence();
            __syncwarp();
            int fcnt = min(sh_fc[wid], KRF * 32);
            kc = run_nms_fb(boxes4, nbox, b, c, cand64, fcnt);
        }

        if (lane >= kc && lane < MAXPC)
            g_keys[(size_t)cls * MAXPC + lane] = 0ull;
    }

    grid_barrier(&g_bar2, grid);

    if (blockIdx.x != 0) return;

    // ================= phase 3: CTA0 finisher (warp wid = batch wid) =========
    {
        const int bb = wid;   // 8 warps == 8 batches
        u64 t[8] = {0, 0, 0, 0, 0, 0, 0, 0};
        #pragma unroll
        for (int j = 0; j < 20; ++j) {
            u64 k = g_keys[(size_t)bb * (NCLS * MAXPC) + j * 32 + lane];
            if (k > t[7]) {
                #pragma unroll
                for (int p = 0; p < 8; ++p)
                    if (k > t[p]) { u64 tmp = t[p]; t[p] = k; k = tmp; }
            }
        }

        u64 mykey = 0ull;
        #pragma unroll
        for (int r = 0; r < 8; ++r) {
            u64 best = warpmax64(t[0]);
            if (lane == r) mykey = best;
            if (t[0] == best) {
                #pragma unroll
                for (int p = 0; p < 7; ++p) t[p] = t[p + 1];
                t[7] = 0ull;
            }
        }

        float s = __uint_as_float((u32)(mykey >> 32));
        bool mask = s > 0.0f;
        if (lane < 8) {
            float4 bx = make_float4(0.f, 0.f, 0.f, 0.f);
            float fcls = 0.f;
            if (mask) {
                int pos  = (int)(mykey & 0xFFFFu);
                int flat = 0x7FFF - (int)((mykey >> 16) & 0x7FFFu);
                fcls = (float)(flat / KCAND);
                float4 gb = g_boxes[(size_t)bb * (NCLS * MAXPC) + pos];
                bx.x = clamp01(gb.x); bx.y = clamp01(gb.y);
                bx.z = clamp01(gb.z); bx.w = clamp01(gb.w);
            }
            int ob = (bb * 8 + lane) * 4;
            out[ob + 0] = bx.x; out[ob + 1] = bx.y;
            out[ob + 2] = bx.z; out[ob + 3] = bx.w;
            out[NB * 8 * 4 + bb * 8 + lane]          = mask ? s : 0.f;    // scores  @256
            out[NB * 8 * 4 + NB * 8 + bb * 8 + lane] = mask ? fcls : 0.f; // classes @320
        }
        u32 vb = __ballot_sync(FULLM, (lane < 8) && mask);
        if (lane == 0)
            out[NB * 8 * 4 + 2 * NB * 8 + bb] = (float)__popc(vb);        // valid @384
    }

    // reset scratch for the next graph replay
    __syncthreads();
    if (tid == 0) { g_bar1 = 0; g_bar2 = 0; }
    for (int i = tid; i < NCLASSES; i += 256) g_cnt[i] = 0;
}

// ---------------------------------------------------------------------------
extern "C" void kernel_launch(void* const* d_in, const int* in_sizes, int n_in,
                              void* d_out, int out_size)
{
    const float* boxes  = (const float*)d_in[0];
    const float* scores = (const float*)d_in[1];
    int nbox = in_sizes[0] / (NB * 4);
    int chunk = (nbox + NCHUNKS - 1) / NCHUNKS;   // grid FIXED at 592 CTAs
    int force_fb = (nbox > 32767) ? 1 : 0;

    fused_kernel<<<NB * NCHUNKS, 256>>>((const float4*)boxes, scores,
                                        (float*)d_out, nbox, chunk, force_fb);
}

// round 14
// speedup vs baseline: 1.1089x; 1.0028x over previous
#include <cuda_runtime.h>

typedef unsigned long long u64;
typedef unsigned int u32;

#define NB        8
#define NCLS      80
#define NCLASSES  (NB * NCLS)      // 640
#define KCAND     256
#define MAXPC     8
#define CSTRIDE32 1280             // u32 slots per class (= 640 u64 fallback view)
#define CAPSC     128              // trusted capture bound (E=64, sigma=8)
#define KRC       4                // u32 keys/lane = 128 sorted slots
#define KRF       20               // u64 keys/lane, fallback
#define LOCCAP    8
#define NCHUNKS   74               // grid = 8*74 = 592 = exactly 4 CTAs/SM * 148
#define THR       0.9968f          // E[captures/class] = 64
#define SBASE     0x3F7F0000u
#define NBUCKETS  1024
#define BATCH     16
#define UNR       8                // independent float4 loads in flight per thread
#define FULLM     0xFFFFFFFFu

static __device__ u32    g_cand[NCLASSES * CSTRIDE32];  // 3.3 MB scratch
static __device__ int    g_cnt[NCLASSES];               // reset by CTA0 each launch
static __device__ u64    g_keys[NCLASSES * MAXPC];
static __device__ float4 g_boxes[NCLASSES * MAXPC];
static __device__ u32    g_hist[NCLASSES * NBUCKETS];   // fallback-only scratch
static __device__ volatile u32 g_bar1, g_bar2;          // reset by CTA0 each launch

__device__ __forceinline__ float clamp01(float x) { return fminf(fmaxf(x, 0.0f), 1.0f); }

__device__ __forceinline__ u64 warpmax64(u64 v)
{
    u32 hi = (u32)(v >> 32);
    u32 hmax = __reduce_max_sync(FULLM, hi);
    u32 lo = (hi == hmax) ? (u32)v : 0u;
    u32 lmax = __reduce_max_sync(FULLM, lo);
    return ((u64)hmax << 32) | lmax;
}

// full resident-grid barrier (co-residency: launch_bounds(256,4), grid = 4*148)
__device__ __forceinline__ void grid_barrier(volatile u32* bar, u32 target)
{
    __syncthreads();
    if (threadIdx.x == 0) {
        __threadfence();
        atomicAdd((u32*)bar, 1u);
        while (*bar < target) __nanosleep(64);
        __threadfence();
    }
    __syncthreads();
}

// ---------------------------------------------------------------------------
// Common path: bitonic-sort 128 u32 keys in registers, then greedy NMS in
// exact rank order. *ranout true iff exit without 8 keeps.
// ---------------------------------------------------------------------------
__device__ int nms_sorted(const float4* __restrict__ boxes4, int nbox, int b, int c,
                          const u32* __restrict__ cand, int cnt, bool* ranout)
{
    const int lane = threadIdx.x & 31;

    u32 kr[KRC];
    #pragma unroll
    for (int r = 0; r < KRC; ++r) {
        int slot = r * 32 + lane;
        kr[r] = (slot < cnt) ? cand[slot] : 0u;
    }

    // bitonic sort, 128 elements, descending; element e = lane + 32*r
    #pragma unroll
    for (int size = 2; size <= 128; size <<= 1) {
        #pragma unroll
        for (int stride = size >> 1; stride > 0; stride >>= 1) {
            if (stride >= 32) {
                const int rs = stride >> 5;
                #pragma unroll
                for (int r = 0; r < KRC; ++r) {
                    if ((r & rs) == 0) {
                        const int r2 = r | rs;
                        const int e = lane + 32 * r;
                        const bool descB = ((e & size) == 0);
                        u32 a = kr[r], d = kr[r2];
                        u32 mx = a > d ? a : d, mn = a > d ? d : a;
                        kr[r]  = descB ? mx : mn;
                        kr[r2] = descB ? mn : mx;
                    }
                }
            } else {
                #pragma unroll
                for (int r = 0; r < KRC; ++r) {
                    const int e = lane + 32 * r;
                    u32 other = __shfl_xor_sync(FULLM, kr[r], stride);
                    const bool iLow  = (lane & stride) == 0;
                    const bool descB = ((e & size) == 0);
                    const bool keepMax = (iLow == descB);
                    u32 mx = kr[r] > other ? kr[r] : other;
                    u32 mn = kr[r] > other ? other : kr[r];
                    kr[r] = keepMax ? mx : mn;
                }
            }
        }
    }

    float4 mykept = make_float4(0.f, 0.f, 0.f, 0.f);
    float  myka   = 0.f;
    int kc = 0;
    bool done = false;

    for (int g = 0; g < KRC && !done; ++g) {
        u32 kg = kr[g];
        float4 obox = make_float4(0.f, 0.f, 0.f, 0.f);
        if (kg) {
            u32 bi = 0x7FFFu - (kg & 0x7FFFu);
            obox = boxes4[(size_t)b * nbox + bi];
        }
        for (int r = 0; r < 32; ++r) {
            u32 key = __shfl_sync(FULLM, kg, r);          // uniform
            if (key == 0u) { done = true; break; }        // uniform
            float4 bx;
            bx.x = __shfl_sync(FULLM, obox.x, r);
            bx.y = __shfl_sync(FULLM, obox.y, r);
            bx.z = __shfl_sync(FULLM, obox.z, r);
            bx.w = __shfl_sync(FULLM, obox.w, r);
            float area = fmaxf(bx.z - bx.x, 0.f) * fmaxf(bx.w - bx.y, 0.f);

            bool supme = false;
            if (lane < kc) {
                float iy1 = fmaxf(bx.x, mykept.x), ix1 = fmaxf(bx.y, mykept.y);
                float iy2 = fminf(bx.z, mykept.z), ix2 = fminf(bx.w, mykept.w);
                float inter = fmaxf(iy2 - iy1, 0.f) * fmaxf(ix2 - ix1, 0.f);
                float uni = area + myka - inter;
                float iou = (uni > 0.f) ? inter / uni : 0.f;
                supme = iou > 0.5f;
            }
            bool keep = (__ballot_sync(FULLM, supme) == 0u);   // uniform

            if (keep) {
                if (lane == kc) {
                    mykept = bx;
                    myka = area;
                    int flat = c * KCAND + g * 32 + r;
                    int pos  = c * MAXPC + kc;
                    g_keys[b * NCLS * MAXPC + pos] =
                        ((u64)((key >> 15) + SBASE) << 32) |
                        ((u64)(u32)(0x7FFF - flat) << 16) | (u32)pos;
                    g_boxes[b * NCLS * MAXPC + pos] = bx;
                }
                ++kc;
                if (kc >= MAXPC) { done = true; break; }  // uniform
            }
        }
    }
    *ranout = (kc < MAXPC);
    return kc;
}

// ---------------------------------------------------------------------------
// Fallback path (u64 keys, REDUX pops) — exact, never expected.
// ---------------------------------------------------------------------------
__device__ int run_nms_fb(const float4* __restrict__ boxes4, int nbox, int b, int c,
                          const u64* __restrict__ cand, int cnt)
{
    const int lane = threadIdx.x & 31;

    u64 kr[KRF];
    #pragma unroll
    for (int r = 0; r < KRF; ++r) {
        int slot = r * 32 + lane;
        kr[r] = (slot < cnt) ? cand[slot] : 0ull;
    }
    u64 mymax = kr[0];
    #pragma unroll
    for (int r = 1; r < KRF; ++r) if (kr[r] > mymax) mymax = kr[r];

    float4 mykept = make_float4(0.f, 0.f, 0.f, 0.f);
    float  myka   = 0.f;
    int kc = 0, totpops = 0;
    bool more = true;

    while (more && kc < MAXPC && totpops < KCAND) {
        const int lim = min(BATCH, KCAND - totpops);
        u64 okey = 0ull;
        int n = 0;
        for (int r = 0; r < lim; ++r) {
            u64 best = warpmax64(mymax);
            if ((u32)(best >> 32) <= 0x3F000000u) break;
            if (lane == r) okey = best;
            if (mymax == best) {
                mymax = 0ull;
                #pragma unroll
                for (int q = 0; q < KRF; ++q) {
                    if (kr[q] == best) kr[q] = 0ull;
                    if (kr[q] > mymax) mymax = kr[q];
                }
            }
            ++n;
        }
        more = (n == lim) && (lim == BATCH);

        float4 obox = make_float4(0.f, 0.f, 0.f, 0.f);
        if (lane < n)
            obox = boxes4[(size_t)b * nbox + (0xFFFFFFFFu - (u32)okey)];

        for (int r = 0; r < n; ++r) {
            float4 bx;
            bx.x = __shfl_sync(FULLM, obox.x, r);
            bx.y = __shfl_sync(FULLM, obox.y, r);
            bx.z = __shfl_sync(FULLM, obox.z, r);
            bx.w = __shfl_sync(FULLM, obox.w, r);
            u64 key = __shfl_sync(FULLM, okey, r);
            float area = fmaxf(bx.z - bx.x, 0.f) * fmaxf(bx.w - bx.y, 0.f);

            bool supme = false;
            if (lane < kc) {
                float iy1 = fmaxf(bx.x, mykept.x), ix1 = fmaxf(bx.y, mykept.y);
                float iy2 = fminf(bx.z, mykept.z), ix2 = fminf(bx.w, mykept.w);
                float inter = fmaxf(iy2 - iy1, 0.f) * fmaxf(ix2 - ix1, 0.f);
                float uni = area + myka - inter;
                float iou = (uni > 0.f) ? inter / uni : 0.f;
                supme = iou > 0.5f;
            }
            bool keep = (__ballot_sync(FULLM, supme) == 0u);

            if (keep) {
                if (lane == kc) {
                    mykept = bx; myka = area;
                    int flat = c * KCAND + totpops + r;
                    int pos  = c * MAXPC + kc;
                    g_keys[b * NCLS * MAXPC + pos] =
                        ((u64)(u32)(key >> 32) << 32) |
                        ((u64)(u32)(0x7FFF - flat) << 16) | (u32)pos;
                    g_boxes[b * NCLS * MAXPC + pos] = bx;
                }
                ++kc;
                if (kc >= MAXPC) return kc;
            }
        }
        totpops += n;
    }
    return kc;
}

// ---------------------------------------------------------------------------
// Fused kernel: scan -> grid barrier -> per-warp NMS -> arrive(+exit) ->
// CTA0 finisher + counter reset. 592 CTAs, all co-resident (4/SM exactly).
// ---------------------------------------------------------------------------
__global__ void __launch_bounds__(256, 4) fused_kernel(
    const float4* __restrict__ boxes4,
    const float*  __restrict__ scores,
    float* __restrict__ out,
    int nbox, int chunk, int force_fb)
{
    const int tid  = threadIdx.x;
    const int lane = tid & 31;
    const int wid  = tid >> 5;
    const u32 grid = gridDim.x;

    __shared__ u32 sh_loc[NCLS * LOCCAP];    // 2.5 KB
    __shared__ int sh_lcnt[NCLS];
    __shared__ int sh_fc[8];

    // ======== phase 1: coalesced scan, 8 independent loads in flight ========
    {
        const int b    = blockIdx.x / NCHUNKS;
        const int ch   = blockIdx.x % NCHUNKS;
        const int box0 = ch * chunk;
        const int boxN = min(chunk, nbox - box0);

        for (int i = tid; i < NCLS; i += 256) sh_lcnt[i] = 0;
        __syncthreads();

        if (boxN > 0) {
            const float4* sp = reinterpret_cast<const float4*>(scores) +
                               (size_t)(b * nbox + box0) * (NCLS / 4);
            const int nf4 = boxN * (NCLS / 4);
            for (int t0 = tid; t0 < nf4; t0 += 256 * UNR) {
                float4 v[UNR];
                #pragma unroll
                for (int u = 0; u < UNR; ++u) {
                    int t = t0 + u * 256;
                    v[u] = (t < nf4) ? __ldcs(sp + t)
                                     : make_float4(0.f, 0.f, 0.f, 0.f);
                }
                #pragma unroll
                for (int u = 0; u < UNR; ++u) {
                    // fast reject: 3 FMAX + 1 compare per float4 (common path)
                    float m = fmaxf(fmaxf(v[u].x, v[u].y), fmaxf(v[u].z, v[u].w));
                    if (m >= THR) {   // rare (~1.3% of float4s)
                        int t = t0 + u * 256;
                        int box = box0 + t / (NCLS / 4);
                        int g   = t % (NCLS / 4);
                        float sv[4] = {v[u].x, v[u].y, v[u].z, v[u].w};
                        #pragma unroll
                        for (int k = 0; k < 4; ++k) {
                            if (sv[k] >= THR) {
                                int c = g * 4 + k;
                                u32 key = ((__float_as_uint(sv[k]) - SBASE) << 15) |
                                          (u32)(0x7FFF - box);
                                int p = atomicAdd(&sh_lcnt[c], 1);
                                if (p < LOCCAP) {
                                    sh_loc[c * LOCCAP + p] = key;
                                } else {  // rare spill (set stays complete)
                                    int q = atomicAdd(&g_cnt[b * NCLS + c], 1);
                                    if (q < CAPSC)
                                        g_cand[(size_t)(b * NCLS + c) * CSTRIDE32 + q] = key;
                                }
                            }
                        }
                    }
                }
            }
        }
        __syncthreads();

        for (int c = tid; c < NCLS; c += 256) {
            int n = min(sh_lcnt[c], LOCCAP);
            if (n > 0) {
                int base = atomicAdd(&g_cnt[b * NCLS + c], n);
                for (int j = 0; j < n; ++j) {
                    int q = base + j;
                    if (q < CAPSC)
                        g_cand[(size_t)(b * NCLS + c) * CSTRIDE32 + q] =
                            sh_loc[c * LOCCAP + j];
                }
            }
        }
    }

    grid_barrier(&g_bar1, grid);

    // ======== phase 2: per-warp NMS (first 640 warps) ========
    const int gw = blockIdx.x * 8 + wid;
    if (gw < NCLASSES) {
        const int cls = gw;
        const int b   = cls / NCLS;
        const int c   = cls % NCLS;
        const u32* cand32 = g_cand + (size_t)cls * CSTRIDE32;
        int cnt = g_cnt[cls];
        int kc = 0;
        bool needfb = force_fb || (cnt > CAPSC) || (cnt <= 0);

        if (!needfb) {
            bool ranout = false;
            kc = nms_sorted(boxes4, nbox, b, c, cand32, cnt, &ranout);
            needfb = ranout;
        }

        if (needfb) {
            // exact histogram rescan in GLOBAL scratch (never expected)
            u64* cand64 = (u64*)cand32;
            u32* hist = g_hist + (size_t)cls * NBUCKETS;
            for (int i = lane; i < NBUCKETS; i += 32) hist[i] = 0;
            __syncwarp();
            for (int i = lane; i < nbox; i += 32) {
                float s = scores[((size_t)b * nbox + i) * NCLS + c];
                atomicAdd(&hist[min((int)(s * (float)NBUCKETS), NBUCKETS - 1)], 1u);
            }
            __syncwarp();
            const int base = lane * 32;
            u32 part = 0;
            #pragma unroll
            for (int j = 0; j < 32; ++j) part += hist[base + j];
            u32 suf = part;
            #pragma unroll
            for (int off = 16; off; off >>= 1) {
                u32 vv = __shfl_down_sync(FULLM, suf, off);
                if (lane + off < 32) suf += vv;
            }
            u32 above = __shfl_down_sync(FULLM, suf, 1);
            if (lane == 31) above = 0;
            int T = -1;
            u32 prev = above;
            for (int bkt = base + 31; bkt >= base; --bkt) {
                u32 cur = prev + hist[bkt];
                if (cur >= KCAND && prev < KCAND) T = bkt;
                prev = cur;
            }
            #pragma unroll
            for (int off = 16; off; off >>= 1)
                T = max(T, __shfl_xor_sync(FULLM, T, off));
            T = max(T, 0);
            if (lane == 0) sh_fc[wid] = 0;
            __syncwarp();
            for (int i = lane; i < nbox; i += 32) {
                float s = scores[((size_t)b * nbox + i) * NCLS + c];
                int bk = min((int)(s * (float)NBUCKETS), NBUCKETS - 1);
                if (bk >= T) {
                    int q = atomicAdd(&sh_fc[wid], 1);
                    if (q < KRF * 32)
                        cand64[q] = ((u64)__float_as_uint(s) << 32) |
                                    (u32)(0xFFFFFFFFu - (u32)i);
                }
            }
            __threadfence();
            __syncwarp();
            int fcnt = min(sh_fc[wid], KRF * 32);
            kc = run_nms_fb(boxes4, nbox, b, c, cand64, fcnt);
        }

        if (lane >= kc && lane < MAXPC)
            g_keys[(size_t)cls * MAXPC + lane] = 0ull;
    }

    // ======== phase 2 epilogue: arrive; only CTA0 waits ========
    __syncthreads();
    if (tid == 0) {
        __threadfence();                      // publish phase-2 writes
        atomicAdd((u32*)&g_bar2, 1u);
    }
    if (blockIdx.x != 0) return;              // non-CTA0 blocks retire now
    if (tid == 0) {
        while (g_bar2 < grid) __nanosleep(64);
        __threadfence();                      // acquire
    }
    __syncthreads();

    // ======== phase 3: CTA0 finisher (warp wid = batch wid) ========
    {
        const int bb = wid;   // 8 warps == 8 batches
        u64 t[8] = {0, 0, 0, 0, 0, 0, 0, 0};
        #pragma unroll
        for (int j = 0; j < 20; ++j) {
            u64 k = g_keys[(size_t)bb * (NCLS * MAXPC) + j * 32 + lane];
            if (k > t[7]) {
                #pragma unroll
                for (int p = 0; p < 8; ++p)
                    if (k > t[p]) { u64 tmp = t[p]; t[p] = k; k = tmp; }
            }
        }

        u64 mykey = 0ull;
        #pragma unroll
        for (int r = 0; r < 8; ++r) {
            u64 best = warpmax64(t[0]);
            if (lane == r) mykey = best;
            if (t[0] == best) {
                #pragma unroll
                for (int p = 0; p < 7; ++p) t[p] = t[p + 1];
                t[7] = 0ull;
            }
        }

        float s = __uint_as_float((u32)(mykey >> 32));
        bool mask = s > 0.0f;
        if (lane < 8) {
            float4 bx = make_float4(0.f, 0.f, 0.f, 0.f);
            float fcls = 0.f;
            if (mask) {
                int pos  = (int)(mykey & 0xFFFFu);
                int flat = 0x7FFF - (int)((mykey >> 16) & 0x7FFFu);
                fcls = (float)(flat / KCAND);
                float4 gb = g_boxes[(size_t)bb * (NCLS * MAXPC) + pos];
                bx.x = clamp01(gb.x); bx.y = clamp01(gb.y);
                bx.z = clamp01(gb.z); bx.w = clamp01(gb.w);
            }
            int ob = (bb * 8 + lane) * 4;
            out[ob + 0] = bx.x; out[ob + 1] = bx.y;
            out[ob + 2] = bx.z; out[ob + 3] = bx.w;
            out[NB * 8 * 4 + bb * 8 + lane]          = mask ? s : 0.f;    // scores  @256
            out[NB * 8 * 4 + NB * 8 + bb * 8 + lane] = mask ? fcls : 0.f; // classes @320
        }
        u32 vb = __ballot_sync(FULLM, (lane < 8) && mask);
        if (lane == 0)
            out[NB * 8 * 4 + 2 * NB * 8 + bb] = (float)__popc(vb);        // valid @384
    }

    // reset scratch for the next graph replay
    __syncthreads();
    if (tid == 0) { g_bar1 = 0; g_bar2 = 0; }
    for (int i = tid; i < NCLASSES; i += 256) g_cnt[i] = 0;
}

// ---------------------------------------------------------------------------
extern "C" void kernel_launch(void* const* d_in, const int* in_sizes, int n_in,
                              void* d_out, int out_size)
{
    const float* boxes  = (const float*)d_in[0];
    const float* scores = (const float*)d_in[1];
    int nbox = in_sizes[0] / (NB * 4);
    int chunk = (nbox + NCHUNKS - 1) / NCHUNKS;   // grid FIXED at 592 CTAs
    int force_fb = (nbox > 32767) ? 1 : 0;

    fused_kernel<<<NB * NCHUNKS, 256>>>((const float4*)boxes, scores,
                                        (float*)d_out, nbox, chunk, force_fb);
}